// round 1
// baseline (speedup 1.0000x reference)
#include <cuda_runtime.h>
#include <cstdint>

#define VOCAB 100000
#define EMB 128
#define N_TOKENS (4096 * 200)

// Scratch: pre-transposed, bias-folded table [VOCAB][EMB]  (51.2 MB)
__device__ float g_table[(size_t)VOCAB * EMB];

// ---------------------------------------------------------------------------
// Kernel 1: table[v][e] = W[e][v] + b[e]   (tiled transpose, bias folded)
// W is [EMB, VOCAB] row-major. TILE=32, blockDim (32, 8).
// grid.x = VOCAB/32 = 3125, grid.y = EMB/32 = 4.
// ---------------------------------------------------------------------------
__global__ __launch_bounds__(256) void transpose_bias_kernel(
    const float* __restrict__ W, const float* __restrict__ b)
{
    __shared__ float tile[32][33];

    const int v0 = blockIdx.x * 32;
    const int e0 = blockIdx.y * 32;
    const int tx = threadIdx.x;   // 0..31
    const int ty = threadIdx.y;   // 0..7

    // Read phase: coalesced along vocab. tile[e_local][v_local]
    #pragma unroll
    for (int i = 0; i < 32; i += 8) {
        tile[ty + i][tx] = W[(size_t)(e0 + ty + i) * VOCAB + (v0 + tx)];
    }
    __syncthreads();

    // Write phase: coalesced along emb. Each thread's emb index is fixed.
    const float bias = b[e0 + tx];
    #pragma unroll
    for (int i = 0; i < 32; i += 8) {
        g_table[(size_t)(v0 + ty + i) * EMB + (e0 + tx)] = tile[tx][ty + i] + bias;
    }
}

// ---------------------------------------------------------------------------
// Kernel 2: gather row + L2 normalize. One warp per token.
// Lane l handles emb dims [4l, 4l+4): float4 load (512B coalesced per token),
// warp shfl reduce for sum of squares, rsqrt, float4 store.
// ---------------------------------------------------------------------------
__global__ __launch_bounds__(256) void gather_norm_kernel(
    const int* __restrict__ x, float* __restrict__ out)
{
    const int gwarp = (blockIdx.x * blockDim.x + threadIdx.x) >> 5;
    const int lane  = threadIdx.x & 31;
    if (gwarp >= N_TOKENS) return;

    const int v = x[gwarp];   // broadcast load (same address per warp)

    const float4* row = reinterpret_cast<const float4*>(g_table + (size_t)v * EMB);
    float4 e = row[lane];

    float s = e.x * e.x + e.y * e.y + e.z * e.z + e.w * e.w;
    #pragma unroll
    for (int off = 16; off > 0; off >>= 1)
        s += __shfl_xor_sync(0xFFFFFFFFu, s, off);

    // ref: e / max(sqrt(s), 1e-12)  ->  e * rsqrt(max(s, 1e-24))
    const float r = rsqrtf(fmaxf(s, 1e-24f));
    e.x *= r; e.y *= r; e.z *= r; e.w *= r;

    float4* orow = reinterpret_cast<float4*>(out + (size_t)gwarp * EMB);
    orow[lane] = e;
}

extern "C" void kernel_launch(void* const* d_in, const int* in_sizes, int n_in,
                              void* d_out, int out_size)
{
    const int*   x = (const int*)d_in[0];    // [4096, 200] int32
    const float* W = (const float*)d_in[1];  // [128, 100000] f32
    const float* b = (const float*)d_in[2];  // [128] f32
    float*     out = (float*)d_out;          // [4096, 200, 128] f32

    dim3 tgrid(VOCAB / 32, EMB / 32);
    dim3 tblk(32, 8);
    transpose_bias_kernel<<<tgrid, tblk>>>(W, b);

    const int threads = 256;                       // 8 warps = 8 tokens / block
    const int blocks  = (N_TOKENS * 32 + threads - 1) / threads;  // 102400
    gather_norm_kernel<<<blocks, threads>>>(x, out);
}

// round 4
// speedup vs baseline: 1.3878x; 1.3878x over previous
#include <cuda_runtime.h>
#include <cstdint>

#define VOCAB 100000
#define EMB 128
#define N_TOKENS (4096 * 200)

// Scratch: pre-transposed, bias-folded, L2-NORMALIZED table [VOCAB][EMB] (51.2 MB)
__device__ float g_table[(size_t)VOCAB * EMB];

// ---------------------------------------------------------------------------
// Kernel 1: table[v][:] = normalize( W[:, v] + b )
// One block = 32 vocab rows x full 128 emb. Block (32, 8) = 256 threads.
// Phase A: coalesced read of W (vocab-contiguous), fold bias, stage into smem
//          tile[v_local][e] (pad 133 -> bank stride 5, conflict-free writes),
//          accumulate per-thread partial sum-of-squares (each thread's 16
//          values all belong to vocab row v0+tx).
// Phase B: reduce 8 partials per row, rsqrt, scale + write coalesced float4.
// ---------------------------------------------------------------------------
__global__ __launch_bounds__(256) void build_table_kernel(
    const float* __restrict__ W, const float* __restrict__ b)
{
    __shared__ float tile[32][133];
    __shared__ float psum[8][32];
    __shared__ float rnorm[32];

    const int v0 = blockIdx.x * 32;
    const int tx = threadIdx.x;   // vocab lane 0..31
    const int ty = threadIdx.y;   // 0..7

    // Phase A: thread (tx,ty) loads e = ec*32 + ty + i for vocab v0+tx.
    float partial = 0.f;
    #pragma unroll
    for (int ec = 0; ec < 4; ec++) {
        #pragma unroll
        for (int i = 0; i < 32; i += 8) {
            const int e = ec * 32 + ty + i;
            const float val = W[(size_t)e * VOCAB + (v0 + tx)] + b[e];
            tile[tx][e] = val;
            partial += val * val;
        }
    }
    psum[ty][tx] = partial;
    __syncthreads();

    if (ty == 0) {
        float s = 0.f;
        #pragma unroll
        for (int j = 0; j < 8; j++) s += psum[j][tx];
        // ref: e / max(sqrt(s), 1e-12)  ->  e * rsqrt(max(s, 1e-24))
        rnorm[tx] = rsqrtf(fmaxf(s, 1e-24f));
    }
    __syncthreads();

    // Phase B: 1024 float4s per block, 4 per thread, coalesced stores.
    const int T = ty * 32 + tx;
    #pragma unroll
    for (int j = 0; j < 4; j++) {
        const int idx = j * 256 + T;     // 0..1023
        const int row = idx >> 5;        // 0..31
        const int c   = (idx & 31) * 4;  // emb float offset
        const float r = rnorm[row];
        float4 o;
        o.x = tile[row][c + 0] * r;
        o.y = tile[row][c + 1] * r;
        o.z = tile[row][c + 2] * r;
        o.w = tile[row][c + 3] * r;
        reinterpret_cast<float4*>(g_table + (size_t)(v0 + row) * EMB)[idx & 31] = o;
    }
}

// ---------------------------------------------------------------------------
// Kernel 2: pure gather copy, MLP=4.
// Flat float4 space: N_TOKENS*32 = 26,214,400 float4s. Each thread handles 4
// independent (token, chunk) pairs spaced nthreads apart. All 4 load chains
// independent -> ~8 loads in flight. Warp-aligned: all lanes of a warp share
// one token (512B contiguous table read), stores fully coalesced.
// ---------------------------------------------------------------------------
#define GATHER_BLOCKS 25600   // N4 / (256*4), exact
#define GATHER_UNROLL 4

__global__ __launch_bounds__(256) void gather_kernel(
    const int* __restrict__ x, float4* __restrict__ out)
{
    const int nthreads = GATHER_BLOCKS * 256;           // 6,553,600
    const int g0 = blockIdx.x * 256 + threadIdx.x;

    float4 v[GATHER_UNROLL];
    #pragma unroll
    for (int u = 0; u < GATHER_UNROLL; u++) {
        const int g = g0 + u * nthreads;
        const int t = g >> 5;            // token
        const int c = g & 31;            // float4 chunk within row
        const int vid = __ldg(&x[t]);    // uniform within warp
        v[u] = reinterpret_cast<const float4*>(g_table + (size_t)vid * EMB)[c];
    }
    #pragma unroll
    for (int u = 0; u < GATHER_UNROLL; u++) {
        out[g0 + u * nthreads] = v[u];
    }
}

extern "C" void kernel_launch(void* const* d_in, const int* in_sizes, int n_in,
                              void* d_out, int out_size)
{
    const int*   x = (const int*)d_in[0];    // [4096, 200] int32
    const float* W = (const float*)d_in[1];  // [128, 100000] f32
    const float* b = (const float*)d_in[2];  // [128] f32
    float4*    out = (float4*)d_out;         // [4096, 200, 128] f32

    build_table_kernel<<<VOCAB / 32, dim3(32, 8)>>>(W, b);
    gather_kernel<<<GATHER_BLOCKS, 256>>>(x, out);
}

// round 5
// speedup vs baseline: 1.5490x; 1.1162x over previous
#include <cuda_runtime.h>
#include <cstdint>

#define VOCAB 100000
#define EMB 128
#define N_TOKENS (4096 * 200)

// Scratch: pre-transposed, bias-folded, L2-NORMALIZED table [VOCAB][EMB] (51.2 MB)
__device__ float g_table[(size_t)VOCAB * EMB];

// ---------------------------------------------------------------------------
// Kernel 1: table[v][:] = normalize( W[:, v] + b )
// One block = 32 vocab rows x full 128 emb. Block (32, 8) = 256 threads.
// ---------------------------------------------------------------------------
__global__ __launch_bounds__(256) void build_table_kernel(
    const float* __restrict__ W, const float* __restrict__ b)
{
    __shared__ float tile[32][133];
    __shared__ float psum[8][32];
    __shared__ float rnorm[32];

    const int v0 = blockIdx.x * 32;
    const int tx = threadIdx.x;   // vocab lane 0..31
    const int ty = threadIdx.y;   // 0..7

    float partial = 0.f;
    #pragma unroll
    for (int ec = 0; ec < 4; ec++) {
        #pragma unroll
        for (int i = 0; i < 32; i += 8) {
            const int e = ec * 32 + ty + i;
            const float val = W[(size_t)e * VOCAB + (v0 + tx)] + b[e];
            tile[tx][e] = val;
            partial += val * val;
        }
    }
    psum[ty][tx] = partial;
    __syncthreads();

    if (ty == 0) {
        float s = 0.f;
        #pragma unroll
        for (int j = 0; j < 8; j++) s += psum[j][tx];
        // ref: e / max(sqrt(s), 1e-12)  ->  e * rsqrt(max(s, 1e-24))
        rnorm[tx] = rsqrtf(fmaxf(s, 1e-24f));
    }
    __syncthreads();

    const int T = ty * 32 + tx;
    #pragma unroll
    for (int j = 0; j < 4; j++) {
        const int idx = j * 256 + T;     // 0..1023
        const int row = idx >> 5;        // 0..31
        const int c   = (idx & 31) * 4;  // emb float offset
        const float r = rnorm[row];
        float4 o;
        o.x = tile[row][c + 0] * r;
        o.y = tile[row][c + 1] * r;
        o.z = tile[row][c + 2] * r;
        o.w = tile[row][c + 3] * r;
        reinterpret_cast<float4*>(g_table + (size_t)(v0 + row) * EMB)[idx & 31] = o;
    }
}

// ---------------------------------------------------------------------------
// Kernel 2: pure gather copy, MLP=8, streaming (evict-first) output stores.
// Table reads use default caching (L2-resident, 8.2x reuse); output uses
// __stcs so the 419 MB write stream doesn't evict the 51 MB table from L2.
// Warp-aligned: all lanes of a warp share one token (512B contiguous read),
// stores fully coalesced.
// ---------------------------------------------------------------------------
#define GATHER_UNROLL 8
#define GATHER_BLOCKS 12800   // N4 / (256*8), exact: 26,214,400 float4s

__global__ __launch_bounds__(256) void gather_kernel(
    const int* __restrict__ x, float4* __restrict__ out)
{
    const int nthreads = GATHER_BLOCKS * 256;           // 3,276,800
    const int g0 = blockIdx.x * 256 + threadIdx.x;

    float4 v[GATHER_UNROLL];
    #pragma unroll
    for (int u = 0; u < GATHER_UNROLL; u++) {
        const int g = g0 + u * nthreads;
        const int t = g >> 5;            // token
        const int c = g & 31;            // float4 chunk within row
        const int vid = __ldg(&x[t]);    // uniform within warp
        v[u] = reinterpret_cast<const float4*>(g_table + (size_t)vid * EMB)[c];
    }
    #pragma unroll
    for (int u = 0; u < GATHER_UNROLL; u++) {
        __stcs(&out[g0 + u * nthreads], v[u]);
    }
}

extern "C" void kernel_launch(void* const* d_in, const int* in_sizes, int n_in,
                              void* d_out, int out_size)
{
    const int*   x = (const int*)d_in[0];    // [4096, 200] int32
    const float* W = (const float*)d_in[1];  // [128, 100000] f32
    const float* b = (const float*)d_in[2];  // [128] f32
    float4*    out = (float4*)d_out;         // [4096, 200, 128] f32

    build_table_kernel<<<VOCAB / 32, dim3(32, 8)>>>(W, b);
    gather_kernel<<<GATHER_BLOCKS, 256>>>(x, out);
}